// round 2
// baseline (speedup 1.0000x reference)
#include <cuda_runtime.h>

// NeuralCDE: B=1024 RK4(3/8) recurrences, 127 steps, 4 F-evals/step.
// Persistent mapping: 128 CTAs x 256 threads, 8 batch rows per CTA.
// W2 (64x1024 fp32): rows 0..43 in SMEM, rows 44..63 in registers (80 regs/thread).
// Core matmul uses Blackwell packed fp32 FMA (fma.rn.f32x2).

#define NB   1024
#define NT   128
#define NI   16
#define NHID 64
#define NOUT 10
#define MR   8
#define NCTA (NB / MR)      // 128
#define NTHR 256
#define KSM  44             // W2 rows held in SMEM
#define KRG  20             // W2 rows held in registers

struct __align__(16) SM {
    float w2[KSM * 1024];   // 180224 B
    float w1[64 * 64];      //  16384 B
    float b2[1024];         //   4096 B
    float wlin[640];        //   2560 B
    float blin[16];         //     64 B
    float b1[64];           //    256 B
    float z[512];           //   2048 B  [hid][row]
    float zp[512];          //   2048 B
    float ks[4][512];       //   8192 B  k1..k4, [hid][row]
    float hdup[64 * 16];    //   4096 B  h duplicated pairs: [hh][2*row..]
    float dx[4 * 8 * 16];   //   2048 B  dX per substep [s][row][ch]
    float p1[4 * 64 * 8];   //   8192 B  mm1 partials / init scratch
};                          // total 230208 B  (< 232448 max dyn smem)

static __device__ __forceinline__ unsigned long long pk(float a, float b) {
    unsigned long long r;
    asm("mov.b64 %0, {%1, %2};" : "=l"(r) : "f"(a), "f"(b));
    return r;
}
static __device__ __forceinline__ void upk(unsigned long long u, float& a, float& b) {
    asm("mov.b64 {%0, %1}, %2;" : "=f"(a), "=f"(b) : "l"(u));
}
static __device__ __forceinline__ void fma2(unsigned long long& d,
                                            unsigned long long a,
                                            unsigned long long b) {
    asm("fma.rn.f32x2 %0, %1, %2, %0;" : "+l"(d) : "l"(a), "l"(b));
}
// tanh(x) = 1 - 2/(exp(2x)+1); ex2/rcp approx -> ~1e-6 abs err, saturates correctly.
static __device__ __forceinline__ float tanh_fast(float x) {
    float e, r;
    asm("ex2.approx.f32 %0, %1;" : "=f"(e) : "f"(x * 2.8853900817779268f));
    asm("rcp.approx.f32 %0, %1;" : "=f"(r) : "f"(e + 1.0f));
    return fmaf(-2.0f, r, 1.0f);
}

__global__ void __launch_bounds__(NTHR, 1)
cde_kernel(const float* __restrict__ ca, const float* __restrict__ cb,
           const float* __restrict__ cc, const float* __restrict__ cd,
           const float* __restrict__ Wi, const float* __restrict__ bi,
           const float* __restrict__ W1, const float* __restrict__ b1g,
           const float* __restrict__ W2, const float* __restrict__ b2g,
           const float* __restrict__ Wl, const float* __restrict__ blg,
           float* __restrict__ out) {
    extern __shared__ __align__(16) char smraw[];
    SM* s = (SM*)smraw;
    const int t  = threadIdx.x;
    const int b0 = blockIdx.x * MR;

    // ---- W2 register tail: rows 44..63, this thread's 4 columns ----
    unsigned long long wr0[KRG], wr1[KRG];
#pragma unroll
    for (int k = 0; k < KRG; k++) {
        float4 v = *(const float4*)(W2 + (KSM + k) * 1024 + 4 * t);
        wr0[k] = pk(v.x, v.y);
        wr1[k] = pk(v.z, v.w);
    }
    // ---- stage weights into SMEM ----
    {
        const float4* src = (const float4*)W2;
        float4* dst = (float4*)s->w2;
        for (int i = t; i < KSM * 256; i += NTHR) dst[i] = src[i];
        for (int i = t; i < 1024; i += NTHR) ((float4*)s->w1)[i] = ((const float4*)W1)[i];
        for (int i = t; i < 256; i += NTHR) ((float4*)s->b2)[i] = ((const float4*)b2g)[i];
        for (int i = t; i < 160; i += NTHR) ((float4*)s->wlin)[i] = ((const float4*)Wl)[i];
        if (t < NOUT) s->blin[t] = blg[t];
        if (t < 64) s->b1[t] = b1g[t];
        // stage W_init (1024 floats) into p1 scratch
        for (int i = t; i < 256; i += NTHR) ((float4*)s->p1)[i] = ((const float4*)Wi)[i];
        // stage coeff_a[:,0] (8x16) into dx[0] scratch
        if (t < 128) {
            int r = t >> 4, i = t & 15;
            s->dx[r * 16 + i] = ca[((size_t)(b0 + r) * 127 + 0) * 16 + i];
        }
    }
    __syncthreads();

    // ---- z0 = coeff_a[:,0] @ W_init + b_init ----
    for (int idx = t; idx < 512; idx += NTHR) {
        int kk = idx >> 3, r = idx & 7;
        float a = bi[kk];
#pragma unroll
        for (int i = 0; i < 16; i++) a = fmaf(s->dx[r * 16 + i], s->p1[i * 64 + kk], a);
        s->z[idx] = a;
    }
    __syncthreads();

    // ================= main time loop =================
    for (int j = 0; j < NT - 1; j++) {
        // Phase A: high threads load coeffs & build dX; low threads emit output row j.
        if (t >= 128) {
            int q = t - 128;
            int r = q >> 4, i = q & 15;
            size_t base = ((size_t)(b0 + r) * 127 + j) * 16 + i;
            float bb = cb[base], c2 = cc[base], d3 = cd[base];
            float old3 = s->dx[(3 * 8 + r) * 16 + i];
            float fj = (float)j;
            float f1 = (fj + (1.0f / 3.0f)) - fj;   // matches reference fp32 frac
            float f2 = (fj + (2.0f / 3.0f)) - fj;
            s->dx[(0 * 8 + r) * 16 + i] = (j == 0) ? bb : old3;  // k1: prev interval, frac=1
            s->dx[(1 * 8 + r) * 16 + i] = fmaf(fmaf(d3, f1, c2), f1, bb);
            s->dx[(2 * 8 + r) * 16 + i] = fmaf(fmaf(d3, f2, c2), f2, bb);
            s->dx[(3 * 8 + r) * 16 + i] = bb + (c2 + d3);        // frac=1
        } else if (t < 80) {
            int r = t / 10, o = t % 10;
            float a = s->blin[o];
#pragma unroll 8
            for (int kk = 0; kk < 64; kk++) a = fmaf(s->z[kk * 8 + r], s->wlin[kk * 10 + o], a);
            out[((size_t)(b0 + r) * NT + j) * NOUT + o] = a;
        }
        __syncthreads();

        // ---- four RK4(3/8) substeps ----
#pragma unroll 1
        for (int ss = 0; ss < 4; ss++) {
            const float* zin = s->z;
            if (ss > 0) {
                for (int idx = t; idx < 512; idx += NTHR) {
                    float zv = s->z[idx];
                    float v;
                    if (ss == 1)      v = fmaf(s->ks[0][idx], (1.0f / 3.0f), zv);
                    else if (ss == 2) v = zv + s->ks[1][idx] - s->ks[0][idx] * (1.0f / 3.0f);
                    else              v = zv + s->ks[0][idx] - s->ks[1][idx] + s->ks[2][idx];
                    s->zp[idx] = v;
                }
                __syncthreads();
                zin = s->zp;
            }
            // ---- mm1: h = relu(z' @ W1 + b1), 4-way K split ----
            {
                int col = t & 63, ksp = t >> 6;
                float a[8];
#pragma unroll
                for (int r = 0; r < 8; r++) a[r] = 0.0f;
                int k0 = ksp * 16;
#pragma unroll
                for (int q = 0; q < 16; q++) {
                    int kk = k0 + q;
                    float4 za = *(const float4*)(zin + kk * 8);
                    float4 zb = *(const float4*)(zin + kk * 8 + 4);
                    float w = s->w1[kk * 64 + col];
                    a[0] = fmaf(za.x, w, a[0]); a[1] = fmaf(za.y, w, a[1]);
                    a[2] = fmaf(za.z, w, a[2]); a[3] = fmaf(za.w, w, a[3]);
                    a[4] = fmaf(zb.x, w, a[4]); a[5] = fmaf(zb.y, w, a[5]);
                    a[6] = fmaf(zb.z, w, a[6]); a[7] = fmaf(zb.w, w, a[7]);
                }
                float4* dst = (float4*)(s->p1 + (ksp * 64 + col) * 8);
                dst[0] = make_float4(a[0], a[1], a[2], a[3]);
                dst[1] = make_float4(a[4], a[5], a[6], a[7]);
            }
            __syncthreads();
            // combine K-split partials, relu, store duplicated pairs {h,h}
            for (int idx = t; idx < 512; idx += NTHR) {
                int col = idx >> 3, r = idx & 7;
                float v = s->b1[col]
                        + s->p1[(0 * 64 + col) * 8 + r] + s->p1[(1 * 64 + col) * 8 + r]
                        + s->p1[(2 * 64 + col) * 8 + r] + s->p1[(3 * 64 + col) * 8 + r];
                v = fmaxf(v, 0.0f);
                *(float2*)(s->hdup + col * 16 + 2 * r) = make_float2(v, v);
            }
            __syncthreads();

            // ---- mm2: g = h @ W2 + b2 (8 rows x 1024 cols), FFMA2 core ----
            unsigned long long acc0[8], acc1[8];
            {
                float4 bv = *(const float4*)(s->b2 + 4 * t);
                unsigned long long q0 = pk(bv.x, bv.y), q1 = pk(bv.z, bv.w);
#pragma unroll
                for (int r = 0; r < 8; r++) { acc0[r] = q0; acc1[r] = q1; }
            }
#pragma unroll 4
            for (int k = 0; k < KSM; k++) {
                const ulonglong2* hp = (const ulonglong2*)(s->hdup + k * 16);
                ulonglong2 hA = hp[0], hB = hp[1], hC = hp[2], hD = hp[3];
                ulonglong2 wv = *(const ulonglong2*)(s->w2 + k * 1024 + 4 * t);
                fma2(acc0[0], hA.x, wv.x); fma2(acc1[0], hA.x, wv.y);
                fma2(acc0[1], hA.y, wv.x); fma2(acc1[1], hA.y, wv.y);
                fma2(acc0[2], hB.x, wv.x); fma2(acc1[2], hB.x, wv.y);
                fma2(acc0[3], hB.y, wv.x); fma2(acc1[3], hB.y, wv.y);
                fma2(acc0[4], hC.x, wv.x); fma2(acc1[4], hC.x, wv.y);
                fma2(acc0[5], hC.y, wv.x); fma2(acc1[5], hC.y, wv.y);
                fma2(acc0[6], hD.x, wv.x); fma2(acc1[6], hD.x, wv.y);
                fma2(acc0[7], hD.y, wv.x); fma2(acc1[7], hD.y, wv.y);
            }
#pragma unroll
            for (int k = 0; k < KRG; k++) {
                const ulonglong2* hp = (const ulonglong2*)(s->hdup + (KSM + k) * 16);
                ulonglong2 hA = hp[0], hB = hp[1], hC = hp[2], hD = hp[3];
                fma2(acc0[0], hA.x, wr0[k]); fma2(acc1[0], hA.x, wr1[k]);
                fma2(acc0[1], hA.y, wr0[k]); fma2(acc1[1], hA.y, wr1[k]);
                fma2(acc0[2], hB.x, wr0[k]); fma2(acc1[2], hB.x, wr1[k]);
                fma2(acc0[3], hB.y, wr0[k]); fma2(acc1[3], hB.y, wr1[k]);
                fma2(acc0[4], hC.x, wr0[k]); fma2(acc1[4], hC.x, wr1[k]);
                fma2(acc0[5], hC.y, wr0[k]); fma2(acc1[5], hC.y, wr1[k]);
                fma2(acc0[6], hD.x, wr0[k]); fma2(acc1[6], hD.x, wr1[k]);
                fma2(acc0[7], hD.y, wr0[k]); fma2(acc1[7], hD.y, wr1[k]);
            }
            // ---- epilogue: tanh + einsum with dX + 4-lane reduce -> k_s ----
            {
                int i0 = (t & 3) * 4, hc = t >> 2;
#pragma unroll
                for (int r = 0; r < 8; r++) {
                    float4 dxv = *(const float4*)(s->dx + (ss * 8 + r) * 16 + i0);
                    float g0, g1, g2, g3;
                    upk(acc0[r], g0, g1);
                    upk(acc1[r], g2, g3);
                    float p = tanh_fast(g0) * dxv.x + tanh_fast(g1) * dxv.y
                            + tanh_fast(g2) * dxv.z + tanh_fast(g3) * dxv.w;
                    p += __shfl_xor_sync(0xffffffffu, p, 1);
                    p += __shfl_xor_sync(0xffffffffu, p, 2);
                    if ((t & 3) == 0) s->ks[ss][hc * 8 + r] = p;
                }
            }
            __syncthreads();
        }
        // ---- zn = z + (k1 + 3(k2+k3) + k4)/8 ----
        for (int idx = t; idx < 512; idx += NTHR) {
            float d = s->ks[0][idx] + 3.0f * (s->ks[1][idx] + s->ks[2][idx]) + s->ks[3][idx];
            s->z[idx] = fmaf(d, 0.125f, s->z[idx]);
        }
        __syncthreads();
    }
    // ---- final output row t = 127 ----
    if (t < 80) {
        int r = t / 10, o = t % 10;
        float a = s->blin[o];
#pragma unroll 8
        for (int kk = 0; kk < 64; kk++) a = fmaf(s->z[kk * 8 + r], s->wlin[kk * 10 + o], a);
        out[((size_t)(b0 + r) * NT + (NT - 1)) * NOUT + o] = a;
    }
}

extern "C" void kernel_launch(void* const* d_in, const int* in_sizes, int n_in,
                              void* d_out, int out_size) {
    // metadata order: times, coeff_a, coeff_b, coeff_two_c, coeff_three_d,
    //                 final_index, W_init, b_init, W1, b1, W2, b2, W_lin, b_lin
    const float* ca = (const float*)d_in[1];
    const float* cb = (const float*)d_in[2];
    const float* cc = (const float*)d_in[3];
    const float* cd = (const float*)d_in[4];
    const float* Wi = (const float*)d_in[6];
    const float* bi = (const float*)d_in[7];
    const float* W1 = (const float*)d_in[8];
    const float* b1 = (const float*)d_in[9];
    const float* W2 = (const float*)d_in[10];
    const float* b2 = (const float*)d_in[11];
    const float* Wl = (const float*)d_in[12];
    const float* bl = (const float*)d_in[13];
    float* out = (float*)d_out;

    size_t smem = sizeof(SM);
    cudaFuncSetAttribute(cde_kernel, cudaFuncAttributeMaxDynamicSharedMemorySize, (int)smem);
    cde_kernel<<<NCTA, NTHR, smem>>>(ca, cb, cc, cd, Wi, bi, W1, b1, W2, b2, Wl, bl, out);
}

// round 3
// speedup vs baseline: 1.0448x; 1.0448x over previous
#include <cuda_runtime.h>

// NeuralCDE: B=1024 RK4(3/8) recurrences, 127 steps, 4 F-evals/step.
// Persistent mapping: 128 CTAs x 256 threads, 8 batch rows per CTA.
// mm2 core: fma.rn.f32x2 with K packed into the two lanes (even/odd-k partials),
// h un-duplicated [r][k] in smem, W2 k-pair-interleaved in smem + 20-row register tail.

#define NB   1024
#define NT   128
#define NI   16
#define NHID 64
#define NOUT 10
#define MR   8
#define NCTA (NB / MR)      // 128
#define NTHR 256
#define KSM  44             // W2 rows held in SMEM (even; 11 quads)
#define KRG  20             // W2 rows held in registers (even; 5 quads)
#define NQS  (KSM / 4)      // 11
#define NQR  (KRG / 4)      // 5

struct __align__(16) SM {
    float w2[KSM * 1024];   // 180224 B  k-pair interleaved: [(k>>1)*2048 + c*2 + (k&1)]
    float w1[64 * 64];      //  16384 B
    float b2[1024];         //   4096 B
    float wlin[640];        //   2560 B
    float blin[16];         //     64 B
    float b1[64];           //    256 B
    float z[512];           //   2048 B  [hid][row]
    float zp[512];          //   2048 B
    float ks[4][512];       //   8192 B  k1..k4, [hid][row]
    float h[8 * 64];        //   2048 B  [row][k]  (un-duplicated, transposed)
    float dx[4 * 8 * 16];   //   2048 B  dX per substep [s][row][ch]
    float p1[4 * 64 * 10];  //  10240 B  mm1 partials (stride 10, 2-way conflict) / init scratch
};                          // total 230208 B (<= 232448 max dyn smem)

static __device__ __forceinline__ unsigned long long pk(float a, float b) {
    unsigned long long r;
    asm("mov.b64 %0, {%1, %2};" : "=l"(r) : "f"(a), "f"(b));
    return r;
}
static __device__ __forceinline__ void upk(unsigned long long u, float& a, float& b) {
    asm("mov.b64 {%0, %1}, %2;" : "=f"(a), "=f"(b) : "l"(u));
}
static __device__ __forceinline__ void fma2(unsigned long long& d,
                                            unsigned long long a,
                                            unsigned long long b) {
    asm("fma.rn.f32x2 %0, %1, %2, %0;" : "+l"(d) : "l"(a), "l"(b));
}
// tanh(x) = 1 - 2/(exp(2x)+1); ex2/rcp approx -> ~1e-6 abs err, saturates correctly.
static __device__ __forceinline__ float tanh_fast(float x) {
    float e, r;
    asm("ex2.approx.f32 %0, %1;" : "=f"(e) : "f"(x * 2.8853900817779268f));
    asm("rcp.approx.f32 %0, %1;" : "=f"(r) : "f"(e + 1.0f));
    return fmaf(-2.0f, r, 1.0f);
}

__global__ void __launch_bounds__(NTHR, 1)
cde_kernel(const float* __restrict__ ca, const float* __restrict__ cb,
           const float* __restrict__ cc, const float* __restrict__ cd,
           const float* __restrict__ Wi, const float* __restrict__ bi,
           const float* __restrict__ W1, const float* __restrict__ b1g,
           const float* __restrict__ W2, const float* __restrict__ b2g,
           const float* __restrict__ Wl, const float* __restrict__ blg,
           float* __restrict__ out) {
    extern __shared__ __align__(16) char smraw[];
    SM* s = (SM*)smraw;
    const int t  = threadIdx.x;
    const int b0 = blockIdx.x * MR;

    // ---- W2 register tail: rows 44..63, this thread's 4 columns, k-pair packed ----
    // wr[p][c] = { W2[44+2p][4t+c], W2[45+2p][4t+c] }
    unsigned long long wr[KRG / 2][4];
#pragma unroll
    for (int p = 0; p < KRG / 2; p++) {
        float4 a = *(const float4*)(W2 + (size_t)(KSM + 2 * p) * 1024 + 4 * t);
        float4 b = *(const float4*)(W2 + (size_t)(KSM + 2 * p + 1) * 1024 + 4 * t);
        wr[p][0] = pk(a.x, b.x);
        wr[p][1] = pk(a.y, b.y);
        wr[p][2] = pk(a.z, b.z);
        wr[p][3] = pk(a.w, b.w);
    }
    // ---- stage weights into SMEM ----
    {
        // W2 rows 0..43 k-pair interleaved: dst[(k>>1)*2048 + c*2 + (k&1)] = W2[k][c]
        for (int i = t; i < KSM * 256; i += NTHR) {
            int k = i >> 8, q = i & 255;           // row k, col quad q
            float4 v = ((const float4*)W2)[i];
            float* d = s->w2 + (k >> 1) * 2048 + (q * 4) * 2 + (k & 1);
            d[0] = v.x; d[2] = v.y; d[4] = v.z; d[6] = v.w;
        }
        for (int i = t; i < 1024; i += NTHR) ((float4*)s->w1)[i] = ((const float4*)W1)[i];
        for (int i = t; i < 256; i += NTHR) ((float4*)s->b2)[i] = ((const float4*)b2g)[i];
        for (int i = t; i < 160; i += NTHR) ((float4*)s->wlin)[i] = ((const float4*)Wl)[i];
        if (t < NOUT) s->blin[t] = blg[t];
        if (t < 64) s->b1[t] = b1g[t];
        // stage W_init (1024 floats) into p1 scratch
        for (int i = t; i < 256; i += NTHR) ((float4*)s->p1)[i] = ((const float4*)Wi)[i];
        // stage coeff_a[:,0] (8x16) into dx[0] scratch
        if (t < 128) {
            int r = t >> 4, i = t & 15;
            s->dx[r * 16 + i] = ca[((size_t)(b0 + r) * 127 + 0) * 16 + i];
        }
    }
    __syncthreads();

    // ---- z0 = coeff_a[:,0] @ W_init + b_init ----
    for (int idx = t; idx < 512; idx += NTHR) {
        int kk = idx >> 3, r = idx & 7;
        float a = bi[kk];
#pragma unroll
        for (int i = 0; i < 16; i++) a = fmaf(s->dx[r * 16 + i], s->p1[i * 64 + kk], a);
        s->z[idx] = a;
    }
    __syncthreads();

    // ================= main time loop =================
    for (int j = 0; j < NT - 1; j++) {
        // Phase A: high threads load coeffs & build dX; low threads emit output row j.
        if (t >= 128) {
            int q = t - 128;
            int r = q >> 4, i = q & 15;
            size_t base = ((size_t)(b0 + r) * 127 + j) * 16 + i;
            float bb = cb[base], c2 = cc[base], d3 = cd[base];
            float old3 = s->dx[(3 * 8 + r) * 16 + i];
            float fj = (float)j;
            float f1 = (fj + (1.0f / 3.0f)) - fj;   // matches reference fp32 frac
            float f2 = (fj + (2.0f / 3.0f)) - fj;
            s->dx[(0 * 8 + r) * 16 + i] = (j == 0) ? bb : old3;  // k1: prev interval, frac=1
            s->dx[(1 * 8 + r) * 16 + i] = fmaf(fmaf(d3, f1, c2), f1, bb);
            s->dx[(2 * 8 + r) * 16 + i] = fmaf(fmaf(d3, f2, c2), f2, bb);
            s->dx[(3 * 8 + r) * 16 + i] = bb + (c2 + d3);        // frac=1
        } else if (t < 80) {
            int r = t / 10, o = t % 10;
            float a = s->blin[o];
#pragma unroll 8
            for (int kk = 0; kk < 64; kk++) a = fmaf(s->z[kk * 8 + r], s->wlin[kk * 10 + o], a);
            out[((size_t)(b0 + r) * NT + j) * NOUT + o] = a;
        }
        __syncthreads();

        // ---- four RK4(3/8) substeps ----
#pragma unroll 1
        for (int ss = 0; ss < 4; ss++) {
            const float* zin = s->z;
            if (ss > 0) {
                for (int idx = t; idx < 512; idx += NTHR) {
                    float zv = s->z[idx];
                    float v;
                    if (ss == 1)      v = fmaf(s->ks[0][idx], (1.0f / 3.0f), zv);
                    else if (ss == 2) v = zv + s->ks[1][idx] - s->ks[0][idx] * (1.0f / 3.0f);
                    else              v = zv + s->ks[0][idx] - s->ks[1][idx] + s->ks[2][idx];
                    s->zp[idx] = v;
                }
                __syncthreads();
                zin = s->zp;
            }
            // ---- mm1: h = relu(z' @ W1 + b1), 4-way K split ----
            {
                int col = t & 63, ksp = t >> 6;
                float a[8];
#pragma unroll
                for (int r = 0; r < 8; r++) a[r] = 0.0f;
                int k0 = ksp * 16;
#pragma unroll
                for (int q = 0; q < 16; q++) {
                    int kk = k0 + q;
                    float4 za = *(const float4*)(zin + kk * 8);
                    float4 zb = *(const float4*)(zin + kk * 8 + 4);
                    float w = s->w1[kk * 64 + col];
                    a[0] = fmaf(za.x, w, a[0]); a[1] = fmaf(za.y, w, a[1]);
                    a[2] = fmaf(za.z, w, a[2]); a[3] = fmaf(za.w, w, a[3]);
                    a[4] = fmaf(zb.x, w, a[4]); a[5] = fmaf(zb.y, w, a[5]);
                    a[6] = fmaf(zb.z, w, a[6]); a[7] = fmaf(zb.w, w, a[7]);
                }
                float* dst = s->p1 + (ksp * 64 + col) * 10;
                *(float2*)(dst + 0) = make_float2(a[0], a[1]);
                *(float2*)(dst + 2) = make_float2(a[2], a[3]);
                *(float2*)(dst + 4) = make_float2(a[4], a[5]);
                *(float2*)(dst + 6) = make_float2(a[6], a[7]);
            }
            __syncthreads();
            // combine K-split partials, relu, store h transposed [r][k]
            for (int idx = t; idx < 512; idx += NTHR) {
                int kk = idx & 63, r = idx >> 6;
                float v = s->b1[kk]
                        + s->p1[(0 * 64 + kk) * 10 + r] + s->p1[(1 * 64 + kk) * 10 + r]
                        + s->p1[(2 * 64 + kk) * 10 + r] + s->p1[(3 * 64 + kk) * 10 + r];
                s->h[r * 64 + kk] = fmaxf(v, 0.0f);
            }
            __syncthreads();

            // ---- mm2: g = h @ W2 + b2 (8 rows x 1024 cols) ----
            // acc[c][r] lanes = (even-k partial, odd-k partial); bias in lane 0.
            unsigned long long acc[4][8];
            {
                float4 bv = *(const float4*)(s->b2 + 4 * t);
                unsigned long long q0 = pk(bv.x, 0.0f), q1 = pk(bv.y, 0.0f);
                unsigned long long q2 = pk(bv.z, 0.0f), q3 = pk(bv.w, 0.0f);
#pragma unroll
                for (int r = 0; r < 8; r++) {
                    acc[0][r] = q0; acc[1][r] = q1; acc[2][r] = q2; acc[3][r] = q3;
                }
            }
#pragma unroll 2
            for (int kq = 0; kq < NQS; kq++) {
                // h quad for each row: {h[r][4kq],h[r][4kq+1]} , {h[r][4kq+2],h[r][4kq+3]}
                ulonglong2 hv[8];
#pragma unroll
                for (int r = 0; r < 8; r++)
                    hv[r] = *(const ulonglong2*)(s->h + r * 64 + 4 * kq);
                const float* wp0 = s->w2 + (size_t)(2 * kq) * 2048 + 8 * t;
                ulonglong2 wA0 = *(const ulonglong2*)(wp0);
                ulonglong2 wB0 = *(const ulonglong2*)(wp0 + 4);
                const float* wp1 = wp0 + 2048;
                ulonglong2 wA1 = *(const ulonglong2*)(wp1);
                ulonglong2 wB1 = *(const ulonglong2*)(wp1 + 4);
#pragma unroll
                for (int r = 0; r < 8; r++) {
                    fma2(acc[0][r], hv[r].x, wA0.x);
                    fma2(acc[1][r], hv[r].x, wA0.y);
                    fma2(acc[2][r], hv[r].x, wB0.x);
                    fma2(acc[3][r], hv[r].x, wB0.y);
                }
#pragma unroll
                for (int r = 0; r < 8; r++) {
                    fma2(acc[0][r], hv[r].y, wA1.x);
                    fma2(acc[1][r], hv[r].y, wA1.y);
                    fma2(acc[2][r], hv[r].y, wB1.x);
                    fma2(acc[3][r], hv[r].y, wB1.y);
                }
            }
            // register tail: rows 44..63, zero smem w-traffic
#pragma unroll
            for (int qq = 0; qq < NQR; qq++) {
                ulonglong2 hv[8];
#pragma unroll
                for (int r = 0; r < 8; r++)
                    hv[r] = *(const ulonglong2*)(s->h + r * 64 + KSM + 4 * qq);
                const int p0 = 2 * qq, p1i = 2 * qq + 1;
#pragma unroll
                for (int r = 0; r < 8; r++) {
                    fma2(acc[0][r], hv[r].x, wr[p0][0]);
                    fma2(acc[1][r], hv[r].x, wr[p0][1]);
                    fma2(acc[2][r], hv[r].x, wr[p0][2]);
                    fma2(acc[3][r], hv[r].x, wr[p0][3]);
                }
#pragma unroll
                for (int r = 0; r < 8; r++) {
                    fma2(acc[0][r], hv[r].y, wr[p1i][0]);
                    fma2(acc[1][r], hv[r].y, wr[p1i][1]);
                    fma2(acc[2][r], hv[r].y, wr[p1i][2]);
                    fma2(acc[3][r], hv[r].y, wr[p1i][3]);
                }
            }
            // ---- epilogue: fold lanes + tanh + einsum with dX + 4-lane reduce ----
            {
                int i0 = (t & 3) * 4, hc = t >> 2;
#pragma unroll
                for (int r = 0; r < 8; r++) {
                    float4 dxv = *(const float4*)(s->dx + (ss * 8 + r) * 16 + i0);
                    float e0, o0, e1, o1, e2, o2, e3, o3;
                    upk(acc[0][r], e0, o0);
                    upk(acc[1][r], e1, o1);
                    upk(acc[2][r], e2, o2);
                    upk(acc[3][r], e3, o3);
                    float p = tanh_fast(e0 + o0) * dxv.x + tanh_fast(e1 + o1) * dxv.y
                            + tanh_fast(e2 + o2) * dxv.z + tanh_fast(e3 + o3) * dxv.w;
                    p += __shfl_xor_sync(0xffffffffu, p, 1);
                    p += __shfl_xor_sync(0xffffffffu, p, 2);
                    if ((t & 3) == 0) s->ks[ss][hc * 8 + r] = p;
                }
            }
            __syncthreads();
        }
        // ---- zn = z + (k1 + 3(k2+k3) + k4)/8 ----
        for (int idx = t; idx < 512; idx += NTHR) {
            float d = s->ks[0][idx] + 3.0f * (s->ks[1][idx] + s->ks[2][idx]) + s->ks[3][idx];
            s->z[idx] = fmaf(d, 0.125f, s->z[idx]);
        }
        __syncthreads();
    }
    // ---- final output row t = 127 ----
    if (t < 80) {
        int r = t / 10, o = t % 10;
        float a = s->blin[o];
#pragma unroll 8
        for (int kk = 0; kk < 64; kk++) a = fmaf(s->z[kk * 8 + r], s->wlin[kk * 10 + o], a);
        out[((size_t)(b0 + r) * NT + (NT - 1)) * NOUT + o] = a;
    }
}

extern "C" void kernel_launch(void* const* d_in, const int* in_sizes, int n_in,
                              void* d_out, int out_size) {
    // metadata order: times, coeff_a, coeff_b, coeff_two_c, coeff_three_d,
    //                 final_index, W_init, b_init, W1, b1, W2, b2, W_lin, b_lin
    const float* ca = (const float*)d_in[1];
    const float* cb = (const float*)d_in[2];
    const float* cc = (const float*)d_in[3];
    const float* cd = (const float*)d_in[4];
    const float* Wi = (const float*)d_in[6];
    const float* bi = (const float*)d_in[7];
    const float* W1 = (const float*)d_in[8];
    const float* b1 = (const float*)d_in[9];
    const float* W2 = (const float*)d_in[10];
    const float* b2 = (const float*)d_in[11];
    const float* Wl = (const float*)d_in[12];
    const float* bl = (const float*)d_in[13];
    float* out = (float*)d_out;

    size_t smem = sizeof(SM);
    cudaFuncSetAttribute(cde_kernel, cudaFuncAttributeMaxDynamicSharedMemorySize, (int)smem);
    cde_kernel<<<NCTA, NTHR, smem>>>(ca, cb, cc, cd, Wi, bi, W1, b1, W2, b2, Wl, bl, out);
}